// round 9
// baseline (speedup 1.0000x reference)
#include <cuda_runtime.h>

// Shapes: L=4, B=8, C=256, H=W=64
#define LN 4
#define BN 8
#define CN 256
#define HW 4096
#define SLABS (LN*BN*CN)        // 8192
#define GRIDN 512
#define TPB 256

__device__ float g_gap[SLABS];
// Monotonic barrier state: never reset, safe across graph replays.
__device__ unsigned g_tickets;
__device__ unsigned g_release;

__device__ __forceinline__ void cp16(float4* smem_dst, const float4* gmem_src) {
    unsigned saddr = (unsigned)__cvta_generic_to_shared(smem_dst);
    asm volatile("cp.async.cg.shared.global [%0], [%1], 16;" :: "r"(saddr), "l"(gmem_src));
}
__device__ __forceinline__ void cp_commit() {
    asm volatile("cp.async.commit_group;");
}
__device__ __forceinline__ void cp_wait_all() {
    asm volatile("cp.async.wait_group 0;" ::: "memory");
}

// Block p: lhi=p>>8, c=p&255. Half-block (128 thr) per slab, l = 2*lhi+slabsel.
// Each iteration handles a batch QUAD: b0=4i held in registers (smem prefetch),
// b1..b3 read twice from global (second touch is an L2 hit; working set ~67MB
// of allocating traffic < 126MB L2). One grid barrier per quad: 2 total.
__global__ __launch_bounds__(TPB, 4) void fused_kernel(const float* __restrict__ in,
                                                       const float* __restrict__ Wlin,
                                                       float* __restrict__ out) {
    const int p       = blockIdx.x;
    const int lhi     = p >> 8;
    const int c       = p & 255;
    const int tid     = threadIdx.x;
    const int slabsel = tid >> 7;
    const int lane    = tid & 127;
    const int l_mine  = 2 * lhi + slabsel;

    __shared__ float4 buf[2048];          // 32 KB: two 16 KB slab chunks
    __shared__ float  s_warp[4][8];
    __shared__ float  s_sc[4][4];         // [batch-in-quad][l]

    float4* mybuf = buf + slabsel * 1024;

    // Prefetch quad 0's b0 into smem (each thread fills exactly its own slots).
    {
        const int slab = (l_mine * BN + 0) * CN + c;
        const float4* src = reinterpret_cast<const float4*>(in) + (size_t)slab * 1024;
#pragma unroll
        for (int j = 0; j < 8; ++j) cp16(mybuf + lane + j * 128, src + lane + j * 128);
        cp_commit();
    }

    for (int i = 0; i < 2; ++i) {
        const int b0 = 4 * i;
        const int slab0 = (l_mine * BN + b0) * CN + c;
        float s[4];

        // ---- b1..b3 GAP sums: allocating loads (lines parked in L2) ----
#pragma unroll
        for (int q = 1; q < 4; ++q) {
            const int slabq = slab0 + q * CN;
            const float4* pq = reinterpret_cast<const float4*>(in) + (size_t)slabq * 1024;
            float acc = 0.0f;
#pragma unroll
            for (int j = 0; j < 8; ++j) {
                float4 t = __ldg(pq + lane + j * 128);
                acc += (t.x + t.y) + (t.z + t.w);
            }
            s[q] = acc;
        }

        // ---- b0: consume smem prefetch into registers ----
        cp_wait_all();
        float4 v[8];
        {
            float acc = 0.0f;
#pragma unroll
            for (int j = 0; j < 8; ++j) {
                v[j] = mybuf[lane + j * 128];
                acc += (v[j].x + v[j].y) + (v[j].z + v[j].w);
            }
            s[0] = acc;
        }

        // ---- Prefetch next quad's b0 (overlaps barrier/scores/stores) ----
        if (i == 0) {
            const int nslab = (l_mine * BN + 4) * CN + c;
            const float4* src = reinterpret_cast<const float4*>(in) + (size_t)nslab * 1024;
#pragma unroll
            for (int j = 0; j < 8; ++j) cp16(mybuf + lane + j * 128, src + lane + j * 128);
            cp_commit();
        }

        // ---- Block reduce 4 sums -> publish 4 gaps ----
#pragma unroll
        for (int off = 16; off; off >>= 1) {
#pragma unroll
            for (int q = 0; q < 4; ++q)
                s[q] += __shfl_down_sync(0xffffffffu, s[q], off);
        }
        if ((tid & 31) == 0) {
#pragma unroll
            for (int q = 0; q < 4; ++q) s_warp[q][tid >> 5] = s[q];
        }
        __syncthreads();
        if (lane == 0) {
            const int base = slabsel * 4;
#pragma unroll
            for (int q = 0; q < 4; ++q) {
                float t = (s_warp[q][base] + s_warp[q][base+1])
                        + (s_warp[q][base+2] + s_warp[q][base+3]);
                g_gap[slab0 + q * CN] = t * (1.0f / (float)HW);
            }
            __threadfence();
        }
        __syncthreads();

        // ---- Grid barrier (monotonic tickets; graph-replay safe) ----
        if (tid == 0) {
            unsigned tk = atomicAdd(&g_tickets, 1u);
            unsigned target = tk / GRIDN + 1u;
            if ((tk + 1u) % GRIDN == 0u) atomicAdd(&g_release, 1u);
            while (*(volatile unsigned*)&g_release < target) __nanosleep(64);
            __threadfence();
        }
        __syncthreads();

        // ---- Scores: warp w handles l = w&3, batches {(w>>2)*2, +1} of quad ----
        {
            const int w  = tid >> 5;
            const int wl = w & 3;
            const int j  = tid & 31;
            const float4* wp = reinterpret_cast<const float4*>(Wlin + (size_t)c * CN) + j * 2;
            float4 w0 = __ldg(wp), w1 = __ldg(wp + 1);
#pragma unroll
            for (int sub = 0; sub < 2; ++sub) {
                const int bq = (w >> 2) * 2 + sub;         // 0..3
                const int b  = b0 + bq;
                const float4* gp = reinterpret_cast<const float4*>(g_gap + (wl * BN + b) * CN) + j * 2;
                float4 g0 = gp[0], g1 = gp[1];
                float sc = g0.x * w0.x + g0.y * w0.y + g0.z * w0.z + g0.w * w0.w
                         + g1.x * w1.x + g1.y * w1.y + g1.z * w1.z + g1.w * w1.w;
#pragma unroll
                for (int off = 16; off; off >>= 1) sc += __shfl_down_sync(0xffffffffu, sc, off);
                if (j == 0) s_sc[bq][wl] = sc;
            }
        }
        __syncthreads();

        // ---- Softmax per batch in quad, pick l_mine ----
        float a[4];
#pragma unroll
        for (int q = 0; q < 4; ++q) {
            float m = fmaxf(fmaxf(s_sc[q][0], s_sc[q][1]), fmaxf(s_sc[q][2], s_sc[q][3]));
            float e0 = __expf(s_sc[q][0]-m), e1 = __expf(s_sc[q][1]-m);
            float e2 = __expf(s_sc[q][2]-m), e3 = __expf(s_sc[q][3]-m);
            a[q] = __expf(s_sc[q][l_mine]-m) / ((e0+e1)+(e2+e3));
        }

        // ---- Store b0 from registers ----
        {
            float4* po = reinterpret_cast<float4*>(out) + (size_t)slab0 * 1024;
#pragma unroll
            for (int j = 0; j < 8; ++j) {
                float4 o = v[j];
                o.x *= a[0]; o.y *= a[0]; o.z *= a[0]; o.w *= a[0];
                __stcs(po + lane + j * 128, o);
            }
        }

        // ---- b1..b3: re-read (L2 hit; oldest first), scale, store ----
#pragma unroll
        for (int q = 1; q < 4; ++q) {
            const int slabq = slab0 + q * CN;
            const float4* pq = reinterpret_cast<const float4*>(in) + (size_t)slabq * 1024;
            float4* po = reinterpret_cast<float4*>(out) + (size_t)slabq * 1024;
            const float aq = a[q];
#pragma unroll
            for (int j = 0; j < 8; ++j) {
                float4 t = __ldcs(pq + lane + j * 128);
                t.x *= aq; t.y *= aq; t.z *= aq; t.w *= aq;
                __stcs(po + lane + j * 128, t);
            }
        }
        __syncthreads();   // protect shared scratch before next quad
    }
}

extern "C" void kernel_launch(void* const* d_in, const int* in_sizes, int n_in,
                              void* d_out, int out_size) {
    const float* in   = (const float*)d_in[0];   // [4,8,256,64,64]
    const float* Wlin = (const float*)d_in[1];   // [256,256]
    float* out = (float*)d_out;

    fused_kernel<<<GRIDN, TPB>>>(in, Wlin, out);
}

// round 10
// speedup vs baseline: 1.0225x; 1.0225x over previous
#include <cuda_runtime.h>

// Shapes: L=4, B=8, C=256, H=W=64
#define LN 4
#define BN 8
#define CN 256
#define HW 4096
#define SLABS (LN*BN*CN)        // 8192
#define GRIDN 512
#define GROUPN 256
#define TPB 256

__device__ float g_gap[SLABS];
// Monotonic per-group barrier state (never reset; graph-replay safe).
__device__ unsigned g_tk[2];
__device__ unsigned g_rel[2];

// cp.async with L2 evict-first policy: smem-path reads must not displace the
// L2-resident b1 lines awaiting their re-read.
__device__ __forceinline__ void cp16_ef(float4* smem_dst, const float4* gmem_src) {
    unsigned saddr = (unsigned)__cvta_generic_to_shared(smem_dst);
    asm volatile(
        "{\n\t.reg .b64 pol;\n\t"
        "createpolicy.fractional.L2::evict_first.b64 pol, 1.0;\n\t"
        "cp.async.cg.shared.global.L2::cache_hint [%0], [%1], 16, pol;\n\t}"
        :: "r"(saddr), "l"(gmem_src));
}
__device__ __forceinline__ void cp_commit() {
    asm volatile("cp.async.commit_group;");
}
__device__ __forceinline__ void cp_wait_all() {
    asm volatile("cp.async.wait_group 0;" ::: "memory");
}

// Group g = p>>8 owns batches 4g..4g+3. Block owns channel c = p&255: all 4
// l-slabs of (b, c). Iteration = batch pair (b0 on-chip, b1 read-twice/L2).
// 2 per-group barriers (domain 256) total.
__global__ __launch_bounds__(TPB, 4) void fused_kernel(const float* __restrict__ in,
                                                       const float* __restrict__ Wlin,
                                                       float* __restrict__ out) {
    const int p   = blockIdx.x;
    const int g   = p >> 8;
    const int c   = p & 255;
    const int tid = threadIdx.x;
    const int bbase = g * 4;

    __shared__ float4 sbuf[2][1024];     // 32 KB: b0 slabs l=2,3
    __shared__ float  s_warp[8][8];      // [slot][warp]
    __shared__ float  s_sc[2][4];        // [batch-in-pair][l]

    // Prefetch iteration 0's smem slabs (b0 = bbase, l = 2,3).
    {
#pragma unroll
        for (int sl = 0; sl < 2; ++sl) {
            const int slab = ((2 + sl) * BN + bbase) * CN + c;
            const float4* src = reinterpret_cast<const float4*>(in) + (size_t)slab * 1024;
#pragma unroll
            for (int k = 0; k < 4; ++k)
                cp16_ef(&sbuf[sl][tid + k * 256], src + tid + k * 256);
        }
        cp_commit();
    }

    for (int i = 0; i < 2; ++i) {
        const int b0 = bbase + 2 * i, b1 = b0 + 1;
        float s[8];
#pragma unroll
        for (int q = 0; q < 8; ++q) s[q] = 0.0f;
        // slot q: bq = q>>2 (0->b0, 1->b1), l = q&3

        // ---- b0 slabs l=0,1 -> registers (evict-first: dead after this) ----
        float4 v[8];
#pragma unroll
        for (int sl = 0; sl < 2; ++sl) {
            const int slab = (sl * BN + b0) * CN + c;
            const float4* src = reinterpret_cast<const float4*>(in) + (size_t)slab * 1024;
#pragma unroll
            for (int k = 0; k < 4; ++k) {
                float4 t = __ldcs(src + tid + k * 256);
                v[sl * 4 + k] = t;
                s[sl] += (t.x + t.y) + (t.z + t.w);
            }
        }

        // ---- b1 all 4 slabs: allocating reads (park in L2 for re-read) ----
#pragma unroll
        for (int l = 0; l < 4; ++l) {
            const int slab = (l * BN + b1) * CN + c;
            const float4* src = reinterpret_cast<const float4*>(in) + (size_t)slab * 1024;
            float acc = 0.0f;
#pragma unroll
            for (int k = 0; k < 4; ++k) {
                float4 t = __ldg(src + tid + k * 256);
                acc += (t.x + t.y) + (t.z + t.w);
            }
            s[4 + l] = acc;
        }

        // ---- b0 slabs l=2,3 from smem (each thread sums slots it copied) ----
        cp_wait_all();
#pragma unroll
        for (int sl = 0; sl < 2; ++sl) {
            float acc = 0.0f;
#pragma unroll
            for (int k = 0; k < 4; ++k) {
                float4 t = sbuf[sl][tid + k * 256];
                acc += (t.x + t.y) + (t.z + t.w);
            }
            s[2 + sl] = acc;
        }

        // ---- Block-reduce 8 sums, publish 8 gaps ----
#pragma unroll
        for (int off = 16; off; off >>= 1) {
#pragma unroll
            for (int q = 0; q < 8; ++q)
                s[q] += __shfl_down_sync(0xffffffffu, s[q], off);
        }
        if ((tid & 31) == 0) {
#pragma unroll
            for (int q = 0; q < 8; ++q) s_warp[q][tid >> 5] = s[q];
        }
        __syncthreads();
        if (tid < 8) {
            float t = 0.0f;
#pragma unroll
            for (int w = 0; w < 8; ++w) t += s_warp[tid][w];
            const int bq = tid >> 2, l = tid & 3;
            g_gap[(l * BN + b0 + bq) * CN + c] = t * (1.0f / (float)HW);
            __threadfence();
        }
        __syncthreads();

        // ---- Per-group barrier (256 blocks; monotonic tickets) ----
        if (tid == 0) {
            unsigned tk = atomicAdd(&g_tk[g], 1u);
            unsigned target = tk / GROUPN + 1u;
            if ((tk + 1u) % GROUPN == 0u) atomicAdd(&g_rel[g], 1u);
            while (*(volatile unsigned*)&g_rel[g] < target) __nanosleep(64);
            __threadfence();
        }
        __syncthreads();

        // ---- Scores: warp w -> batch bq=w>>2, level l=w&3; 256-c dot ----
        {
            const int w = tid >> 5, j = tid & 31;
            const int bq = w >> 2, l = w & 3, b = b0 + bq;
            const float4* gp = reinterpret_cast<const float4*>(g_gap + (l * BN + b) * CN) + j * 2;
            const float4* wp = reinterpret_cast<const float4*>(Wlin + (size_t)c * CN) + j * 2;
            float4 g0 = gp[0], g1 = gp[1];
            float4 w0 = __ldg(wp), w1 = __ldg(wp + 1);
            float sc = g0.x * w0.x + g0.y * w0.y + g0.z * w0.z + g0.w * w0.w
                     + g1.x * w1.x + g1.y * w1.y + g1.z * w1.z + g1.w * w1.w;
#pragma unroll
            for (int off = 16; off; off >>= 1) sc += __shfl_down_sync(0xffffffffu, sc, off);
            if (j == 0) s_sc[bq][l] = sc;
        }
        __syncthreads();

        // ---- Softmax per batch (redundant per thread) ----
        float a[2][4];
#pragma unroll
        for (int bq = 0; bq < 2; ++bq) {
            float m = fmaxf(fmaxf(s_sc[bq][0], s_sc[bq][1]), fmaxf(s_sc[bq][2], s_sc[bq][3]));
            float e0 = __expf(s_sc[bq][0] - m), e1 = __expf(s_sc[bq][1] - m);
            float e2 = __expf(s_sc[bq][2] - m), e3 = __expf(s_sc[bq][3] - m);
            float inv = 1.0f / ((e0 + e1) + (e2 + e3));
            a[bq][0] = e0 * inv; a[bq][1] = e1 * inv;
            a[bq][2] = e2 * inv; a[bq][3] = e3 * inv;
        }

        // ---- Store b0 l=0,1 from registers ----
#pragma unroll
        for (int sl = 0; sl < 2; ++sl) {
            const int slab = (sl * BN + b0) * CN + c;
            float4* po = reinterpret_cast<float4*>(out) + (size_t)slab * 1024;
            const float aa = a[0][sl];
#pragma unroll
            for (int k = 0; k < 4; ++k) {
                float4 o = v[sl * 4 + k];
                o.x *= aa; o.y *= aa; o.z *= aa; o.w *= aa;
                __stcs(po + tid + k * 256, o);
            }
        }

        // ---- Store b0 l=2,3 from smem ----
#pragma unroll
        for (int sl = 0; sl < 2; ++sl) {
            const int slab = ((2 + sl) * BN + b0) * CN + c;
            float4* po = reinterpret_cast<float4*>(out) + (size_t)slab * 1024;
            const float aa = a[0][2 + sl];
#pragma unroll
            for (int k = 0; k < 4; ++k) {
                float4 o = sbuf[sl][tid + k * 256];
                o.x *= aa; o.y *= aa; o.z *= aa; o.w *= aa;
                __stcs(po + tid + k * 256, o);
            }
        }

        // ---- b1: re-read (L2 hit), scale, store ----
#pragma unroll
        for (int l = 0; l < 4; ++l) {
            const int slab = (l * BN + b1) * CN + c;
            const float4* pq = reinterpret_cast<const float4*>(in) + (size_t)slab * 1024;
            float4* po = reinterpret_cast<float4*>(out) + (size_t)slab * 1024;
            const float aa = a[1][l];
#pragma unroll
            for (int k = 0; k < 4; ++k) {
                float4 t = __ldcs(pq + tid + k * 256);
                t.x *= aa; t.y *= aa; t.z *= aa; t.w *= aa;
                __stcs(po + tid + k * 256, t);
            }
        }

        // ---- Prefetch next iteration's smem slabs (own slots already
        //      consumed above; per-thread ordering makes this safe) ----
        if (i == 0) {
#pragma unroll
            for (int sl = 0; sl < 2; ++sl) {
                const int slab = ((2 + sl) * BN + bbase + 2) * CN + c;
                const float4* src = reinterpret_cast<const float4*>(in) + (size_t)slab * 1024;
#pragma unroll
                for (int k = 0; k < 4; ++k)
                    cp16_ef(&sbuf[sl][tid + k * 256], src + tid + k * 256);
            }
            cp_commit();
        }
        __syncthreads();   // protect shared scratch before next iteration
    }
}

extern "C" void kernel_launch(void* const* d_in, const int* in_sizes, int n_in,
                              void* d_out, int out_size) {
    const float* in   = (const float*)d_in[0];   // [4,8,256,64,64]
    const float* Wlin = (const float*)d_in[1];   // [256,256]
    float* out = (float*)d_out;

    fused_kernel<<<GRIDN, TPB>>>(in, Wlin, out);
}

// round 11
// speedup vs baseline: 1.0986x; 1.0744x over previous
#include <cuda_runtime.h>

// Shapes: L=4, B=8, C=256, H=W=64
#define LN 4
#define BN 8
#define CN 256
#define HW 4096
#define PBLK 256                 // producer blocks: one per channel c
#define CBLK (BN*CN)             // 2048 consumer blocks: one per (b,c)
#define READY_TARGET (PBLK*LN)   // 4 gap-publishing threads per producer block

__device__ float g_gap[LN*BN*CN];
__device__ int   g_ready[BN];

// Zero the per-batch ready counters each call (graph-replay safe).
__global__ void init_kernel() {
    if (threadIdx.x < BN) g_ready[threadIdx.x] = 0;
}

__global__ __launch_bounds__(256) void main_kernel(const float* __restrict__ in,
                                                   const float* __restrict__ Wlin,
                                                   float* __restrict__ out) {
    const int bid = blockIdx.x;
    const int tid = threadIdx.x;

    if (bid < PBLK) {
        // ================= PRODUCER: channel c = bid =================
        const int c = bid;
        __shared__ float s_warp[LN][8];

        for (int b = 0; b < BN; ++b) {
            float acc[LN];
#pragma unroll
            for (int l = 0; l < LN; ++l) {
                const float4* p = reinterpret_cast<const float4*>(in)
                                + (size_t)((l * BN + b) * CN + c) * 1024;
                float a = 0.0f;
#pragma unroll
                for (int k = 0; k < 4; ++k) {
                    float4 v = p[tid + k * 256];     // default load: park line in L2
                    a += (v.x + v.y) + (v.z + v.w);
                }
                acc[l] = a;
            }
#pragma unroll
            for (int off = 16; off; off >>= 1) {
#pragma unroll
                for (int l = 0; l < LN; ++l)
                    acc[l] += __shfl_down_sync(0xffffffffu, acc[l], off);
            }
            if ((tid & 31) == 0) {
#pragma unroll
                for (int l = 0; l < LN; ++l) s_warp[l][tid >> 5] = acc[l];
            }
            __syncthreads();
            if (tid < LN) {
                float t = 0.0f;
#pragma unroll
                for (int w = 0; w < 8; ++w) t += s_warp[tid][w];
                __stcg(&g_gap[(tid * BN + b) * CN + c], t * (1.0f / (float)HW));
                __threadfence();                      // release: gap before ticket
                atomicAdd(&g_ready[b], 1);
            }
            __syncthreads();
        }
    } else {
        // ================= CONSUMER: q -> (b, c) =================
        const int q = bid - PBLK;
        const int b = q >> 8;
        const int c = q & 255;
        __shared__ float s_sc[LN];

        // Spin until batch b's gaps are fully published (volatile L2 poll).
        if (tid == 0) {
            int r;
            while (true) {
                asm volatile("ld.global.cg.s32 %0, [%1];" : "=r"(r) : "l"(&g_ready[b]));
                if (r >= READY_TARGET) break;
                __nanosleep(128);
            }
        }
        __syncthreads();   // all threads ordered after the flag observation

        // Scores: warp w computes l=w; lane j covers c' = j*8..j*8+7.
        const int w = tid >> 5, j = tid & 31;
        if (w < LN) {
            const float4* gp = reinterpret_cast<const float4*>(g_gap + (w * BN + b) * CN) + j * 2;
            const float4* wp = reinterpret_cast<const float4*>(Wlin + (size_t)c * CN) + j * 2;
            float4 g0 = gp[0], g1 = gp[1];
            float4 w0 = __ldg(wp), w1 = __ldg(wp + 1);
            float sc = g0.x * w0.x + g0.y * w0.y + g0.z * w0.z + g0.w * w0.w
                     + g1.x * w1.x + g1.y * w1.y + g1.z * w1.z + g1.w * w1.w;
#pragma unroll
            for (int off = 16; off; off >>= 1) sc += __shfl_down_sync(0xffffffffu, sc, off);
            if (j == 0) s_sc[w] = sc;
        }
        __syncthreads();

        // Softmax over L (redundant per thread — trivial).
        float m = fmaxf(fmaxf(s_sc[0], s_sc[1]), fmaxf(s_sc[2], s_sc[3]));
        float e0 = __expf(s_sc[0] - m), e1 = __expf(s_sc[1] - m);
        float e2 = __expf(s_sc[2] - m), e3 = __expf(s_sc[3] - m);
        float inv = 1.0f / ((e0 + e1) + (e2 + e3));
        float attn[LN] = {e0 * inv, e1 * inv, e2 * inv, e3 * inv};

        // Scale the 4 slabs: reads trail the producer by ~1 batch -> L2 hits.
#pragma unroll
        for (int l = 0; l < LN; ++l) {
            const size_t slab = (size_t)((l * BN + b) * CN + c);
            const float4* pi = reinterpret_cast<const float4*>(in) + slab * 1024;
            float4* po = reinterpret_cast<float4*>(out) + slab * 1024;
            const float a = attn[l];
#pragma unroll
            for (int k = 0; k < 4; ++k) {
                float4 v = __ldcs(pi + tid + k * 256);   // dead after read
                v.x *= a; v.y *= a; v.z *= a; v.w *= a;
                __stcs(po + tid + k * 256, v);           // evict-first: don't churn L2
            }
        }
    }
}

extern "C" void kernel_launch(void* const* d_in, const int* in_sizes, int n_in,
                              void* d_out, int out_size) {
    const float* in   = (const float*)d_in[0];   // [4,8,256,64,64]
    const float* Wlin = (const float*)d_in[1];   // [256,256]
    float* out = (float*)d_out;

    init_kernel<<<1, 32>>>();
    main_kernel<<<PBLK + CBLK, 256>>>(in, Wlin, out);
}